// round 7
// baseline (speedup 1.0000x reference)
#include <cuda_runtime.h>
#include <cuda_bf16.h>

// SparseDualFlow: reference = 100-iter Nesterov proximal loop per element.
// Linear recurrence per element; relu never clips for d>0, flow==0 for d<=0,
// global convergence flag can't fire before iter ~133 > 100.
// => flow_100 = K * max(d, 0). K computed host-side (exact recurrence, d=1).
//
// R7: BATCH scaling trend (1->4: -0.54us, 4->8: -0.48us) at 7.38 TB/s
// apparent (92% of spec). One more doubling: BATCH=16, grid 1024. Occupancy
// is provably irrelevant here (48% -> faster at R6), so the reg-pressure
// occupancy drop is acceptable. Floor ~17.5us; this is the last lever.

#define BATCH 16

__global__ void sparse_dual_flow_kernel(const float4* __restrict__ in,
                                        float4* __restrict__ out,
                                        float K, int n4) {
    int base = blockIdx.x * (blockDim.x * BATCH) + threadIdx.x;

    if (base + (BATCH - 1) * blockDim.x < n4) {   // fast path (always, n = 2^24)
        float4 v[BATCH];
        #pragma unroll
        for (int k = 0; k < BATCH; ++k)
            v[k] = __ldcs(&in[base + k * blockDim.x]);   // front-batched loads
        #pragma unroll
        for (int k = 0; k < BATCH; ++k) {
            float4 r;
            r.x = fmaxf(K * v[k].x, 0.0f);
            r.y = fmaxf(K * v[k].y, 0.0f);
            r.z = fmaxf(K * v[k].z, 0.0f);
            r.w = fmaxf(K * v[k].w, 0.0f);
            __stcs(&out[base + k * blockDim.x], r);
        }
    } else {
        #pragma unroll
        for (int k = 0; k < BATCH; ++k) {
            int i = base + k * blockDim.x;
            if (i < n4) {
                float4 d = __ldcs(&in[i]);
                float4 r;
                r.x = fmaxf(K * d.x, 0.0f);
                r.y = fmaxf(K * d.y, 0.0f);
                r.z = fmaxf(K * d.z, 0.0f);
                r.w = fmaxf(K * d.w, 0.0f);
                __stcs(&out[i], r);
            }
        }
    }
}

__global__ void sparse_dual_flow_tail(const float* __restrict__ in,
                                      float* __restrict__ out,
                                      float K, int start, int n) {
    int i = start + blockIdx.x * blockDim.x + threadIdx.x;
    if (i < n) out[i] = fmaxf(K * in[i], 0.0f);
}

static float compute_K() {
    // Exact reference recurrence (reference op order) in double with d = 1.
    const double STEP_SIZE = 0.01, MOMENTUM = 0.9;
    double flow = 0.0, acc = 0.0;
    for (int t = 0; t < 100; ++t) {
        double acc_m = MOMENTUM * acc;
        double gradient = 2.0 * (flow - acc_m) - 1.0;  // d = 1
        double next_acc = acc_m + STEP_SIZE * gradient;
        double next_flow = flow - next_acc;
        if (next_flow < 0.0) next_flow = 0.0;
        flow = next_flow;
        acc = next_acc;
    }
    return (float)flow;
}

extern "C" void kernel_launch(void* const* d_in, const int* in_sizes, int n_in,
                              void* d_out, int out_size) {
    const float* dual = (const float*)d_in[0];
    float* out = (float*)d_out;
    int n = in_sizes[0];

    float K = compute_K();  // host-side, baked as kernel arg at capture time

    int n4 = n / 4;
    if (n4 > 0) {
        const int threads = 256;
        int tile = threads * BATCH;
        int blocks = (n4 + tile - 1) / tile;
        sparse_dual_flow_kernel<<<blocks, threads>>>(
            (const float4*)dual, (float4*)out, K, n4);
    }
    int rem = n - n4 * 4;
    if (rem > 0) {
        sparse_dual_flow_tail<<<1, 64>>>(dual, out, K, n4 * 4, n);
    }
}

// round 8
// speedup vs baseline: 1.0763x; 1.0763x over previous
#include <cuda_runtime.h>
#include <cuda_bf16.h>

// SparseDualFlow: reference = 100-iter Nesterov proximal loop per element.
// Linear recurrence per element; relu never clips for d>0, flow==0 for d<=0,
// global convergence flag can't fire before iter ~133 > 100.
// => flow_100 = K * max(d, 0). K computed host-side (exact recurrence, d=1).
//
// FINAL (R8 = R6 winner, reverted from BATCH=16): BATCH scan B4/B8/B16 gave
// kernel 18.66/18.18/18.08us -- saturated at ~7.4 TB/s apparent (92% of
// 8TB/s HBM spec). B8 had the best end-to-end dur (21.2us). Occupancy 48%
// vs 20% made no difference: in-flight-bytes-limited. Converged at the
// memory floor; the dominant win was the algebraic loop collapse.

#define BATCH 8

__global__ void sparse_dual_flow_kernel(const float4* __restrict__ in,
                                        float4* __restrict__ out,
                                        float K, int n4) {
    int base = blockIdx.x * (blockDim.x * BATCH) + threadIdx.x;

    if (base + (BATCH - 1) * blockDim.x < n4) {   // fast path (always, n = 2^24)
        float4 v[BATCH];
        #pragma unroll
        for (int k = 0; k < BATCH; ++k)
            v[k] = __ldcs(&in[base + k * blockDim.x]);   // front-batched loads
        #pragma unroll
        for (int k = 0; k < BATCH; ++k) {
            float4 r;
            r.x = fmaxf(K * v[k].x, 0.0f);
            r.y = fmaxf(K * v[k].y, 0.0f);
            r.z = fmaxf(K * v[k].z, 0.0f);
            r.w = fmaxf(K * v[k].w, 0.0f);
            __stcs(&out[base + k * blockDim.x], r);
        }
    } else {
        #pragma unroll
        for (int k = 0; k < BATCH; ++k) {
            int i = base + k * blockDim.x;
            if (i < n4) {
                float4 d = __ldcs(&in[i]);
                float4 r;
                r.x = fmaxf(K * d.x, 0.0f);
                r.y = fmaxf(K * d.y, 0.0f);
                r.z = fmaxf(K * d.z, 0.0f);
                r.w = fmaxf(K * d.w, 0.0f);
                __stcs(&out[i], r);
            }
        }
    }
}

__global__ void sparse_dual_flow_tail(const float* __restrict__ in,
                                      float* __restrict__ out,
                                      float K, int start, int n) {
    int i = start + blockIdx.x * blockDim.x + threadIdx.x;
    if (i < n) out[i] = fmaxf(K * in[i], 0.0f);
}

static float compute_K() {
    // Exact reference recurrence (reference op order) in double with d = 1.
    const double STEP_SIZE = 0.01, MOMENTUM = 0.9;
    double flow = 0.0, acc = 0.0;
    for (int t = 0; t < 100; ++t) {
        double acc_m = MOMENTUM * acc;
        double gradient = 2.0 * (flow - acc_m) - 1.0;  // d = 1
        double next_acc = acc_m + STEP_SIZE * gradient;
        double next_flow = flow - next_acc;
        if (next_flow < 0.0) next_flow = 0.0;
        flow = next_flow;
        acc = next_acc;
    }
    return (float)flow;
}

extern "C" void kernel_launch(void* const* d_in, const int* in_sizes, int n_in,
                              void* d_out, int out_size) {
    const float* dual = (const float*)d_in[0];
    float* out = (float*)d_out;
    int n = in_sizes[0];

    float K = compute_K();  // host-side, baked as kernel arg at capture time

    int n4 = n / 4;
    if (n4 > 0) {
        const int threads = 256;
        int tile = threads * BATCH;
        int blocks = (n4 + tile - 1) / tile;
        sparse_dual_flow_kernel<<<blocks, threads>>>(
            (const float4*)dual, (float4*)out, K, n4);
    }
    int rem = n - n4 * 4;
    if (rem > 0) {
        sparse_dual_flow_tail<<<1, 64>>>(dual, out, K, n4 * 4, n);
    }
}